// round 17
// baseline (speedup 1.0000x reference)
#include <cuda_runtime.h>
#include <cuda_fp16.h>
#include <cstdint>
#include <cstddef>

#define DEVINL __device__ __forceinline__

// ---------------- problem dims ----------------
constexpr int Bdim = 4, Tdim = 256, Udim = 64, Ddim = 512, Jdim = 1024, Vdim = 1024;
constexpr int Mtot = Bdim * Tdim * Udim;  // 65536
constexpr int NMT = Mtot / 16;            // 4096 m-tiles (main GEMM)
constexpr int NKT = Jdim / 16;            // 64 k-tiles (main GEMM)
constexpr int NNT = Vdim / 16;            // 64 n-tiles
constexpr int NKTP = Ddim / 16;           // 32 k-tiles (proj GEMMs)
constexpr int NTILES = NMT / 8 * 8 * 8 / 8;  // 4096*8/8 ... (kept simple below)
constexpr int GEMM_GRID = 304;            // 2 CTAs/SM x 152 SMs (GB300)

// ---------------- device scratch (allocs forbidden) ----------------
__device__ float g_enc_out[Bdim * Tdim * Jdim];   // 4 MB
__device__ float g_pred_out[Bdim * Udim * Jdim];  // 1 MB
// fragment-packed operands: tile (16x16 fp16) = 32 lanes x uint4
__device__ uint4 g_Aft[(size_t)NMT * NKT * 32];   // 134 MB  tanh(joint)
__device__ uint4 g_Bft[(size_t)NNT * NKT * 32];   // 2 MB    W_out^T frags
// proj operands (fp16 fragment tiles)
__device__ uint4 g_enc_pk[2048 * 32];             // enc   [1024,512]  64mt x 32kt
__device__ uint4 g_pred_pk[512 * 32];             // pred  [256,512]   16mt x 32kt
__device__ uint4 g_Wenc_pk[2048 * 32];            // W_enc [512,1024]  64nt x 32kt
__device__ uint4 g_Wpred_pk[2048 * 32];           // W_pred same shape

// ---------------- PTX helpers ----------------
DEVINL void mma_fp16(float& c0, float& c1, float& c2, float& c3,
                     uint32_t a0, uint32_t a1, uint32_t a2, uint32_t a3,
                     uint32_t b0, uint32_t b1) {
    asm volatile(
        "mma.sync.aligned.m16n8k16.row.col.f32.f16.f16.f32 "
        "{%0,%1,%2,%3}, {%4,%5,%6,%7}, {%8,%9}, {%0,%1,%2,%3};"
        : "+f"(c0), "+f"(c1), "+f"(c2), "+f"(c3)
        : "r"(a0), "r"(a1), "r"(a2), "r"(a3), "r"(b0), "r"(b1));
}
DEVINL uint4 ldg_nc(const uint4* p) {
    uint4 v;
    asm("ld.global.nc.v4.u32 {%0,%1,%2,%3}, [%4];"
        : "=r"(v.x), "=r"(v.y), "=r"(v.z), "=r"(v.w) : "l"(p));
    return v;
}
DEVINL float tanh_fast(float x) {
    float y;
    asm("tanh.approx.f32 %0, %1;" : "=f"(y) : "f"(x));
    return y;
}
DEVINL uint32_t pack_h2(float lo, float hi) {
    __half2 h = __floats2half2_rn(lo, hi);
    return *(uint32_t*)&h;
}

// ======== fragment tile packers ========
DEVINL void apack_tile(uint4* dst, const float* __restrict__ X, int mt, int kt,
                       int K, int nkt, int lane) {
    int gr = lane >> 2, kc = (lane & 3) * 2;
    const float* p = X + (size_t)(mt * 16 + gr) * K + kt * 16 + kc;
    const float* q = p + (size_t)8 * K;
    uint4 o;
    o.x = pack_h2(p[0], p[1]);
    o.y = pack_h2(q[0], q[1]);
    o.z = pack_h2(p[8], p[9]);
    o.w = pack_h2(q[8], q[9]);
    dst[((size_t)mt * nkt + kt) * 32 + lane] = o;
}
DEVINL void bpack_tile(uint4* dst, const float* __restrict__ W, int nt, int kt,
                       int nkt, int N, int lane) {
    int c = lane >> 2, kc = (lane & 3) * 2;
    int k0 = kt * 16 + kc;
    int n_lo = nt * 16 + c, n_hi = n_lo + 8;
    uint4 o;
    o.x = pack_h2(W[(size_t)k0 * N + n_lo],       W[(size_t)(k0 + 1) * N + n_lo]);
    o.y = pack_h2(W[(size_t)(k0 + 8) * N + n_lo], W[(size_t)(k0 + 9) * N + n_lo]);
    o.z = pack_h2(W[(size_t)k0 * N + n_hi],       W[(size_t)(k0 + 1) * N + n_hi]);
    o.w = pack_h2(W[(size_t)(k0 + 8) * N + n_hi], W[(size_t)(k0 + 9) * N + n_hi]);
    dst[((size_t)nt * nkt + kt) * 32 + lane] = o;
}

// ======== kernel 0: pack everything to fp16 fragment tiles ========
__global__ __launch_bounds__(256) void pack_kernel(
    const float* __restrict__ enc, const float* __restrict__ pred,
    const float* __restrict__ W_enc, const float* __restrict__ W_pred,
    const float* __restrict__ W_out) {
    int wu = blockIdx.x * 8 + (threadIdx.x >> 5);
    int lane = threadIdx.x & 31;
    if (wu < 2048) {
        apack_tile(g_enc_pk, enc, wu >> 5, wu & 31, Ddim, NKTP, lane);
    } else if (wu < 2560) {
        int t = wu - 2048;
        apack_tile(g_pred_pk, pred, t >> 5, t & 31, Ddim, NKTP, lane);
    } else if (wu < 4608) {
        int t = wu - 2560;
        bpack_tile(g_Wenc_pk, W_enc, t >> 5, t & 31, NKTP, Jdim, lane);
    } else if (wu < 6656) {
        int t = wu - 4608;
        bpack_tile(g_Wpred_pk, W_pred, t >> 5, t & 31, NKTP, Jdim, lane);
    } else {
        int t = wu - 6656;
        bpack_tile(g_Bft, W_out, t >> 6, t & 63, NKT, Vdim, lane);
    }
}

// ======== kernel 1: proj GEMMs (fp16 frags, fp32 out + bias) ========
__global__ __launch_bounds__(256) void proj_gemm_kernel(
    const float* __restrict__ b_enc, const float* __restrict__ b_pred) {
    __shared__ float bias_s[128];
    int tid = threadIdx.x;
    int lane = tid & 31;
    int wid = tid >> 5;
    int wm = wid >> 2;        // 0..1 (32-row slab)
    int wn = wid & 3;         // 0..3 (32-col slab)

    bool is_enc = blockIdx.y < 16;
    const uint4* apk = is_enc ? g_enc_pk : g_pred_pk;
    const uint4* bpk = is_enc ? g_Wenc_pk : g_Wpred_pk;
    float* C = is_enc ? g_enc_out : g_pred_out;
    const float* bias = is_enc ? b_enc : b_pred;
    int m0 = (is_enc ? blockIdx.y : blockIdx.y - 16) * 64;
    int n0 = blockIdx.x * 128;

    if (tid < 128) bias_s[tid] = bias[n0 + tid];
    __syncthreads();

    int mt_base = (m0 >> 4) + wm * 2;
    int nt_base = (n0 >> 4) + wn * 2;
    const uint4* aQ = apk + ((size_t)mt_base << 10) + lane;
    const uint4* bQ = bpk + ((size_t)nt_base << 10) + lane;

    float acc[2][4][4];
#pragma unroll
    for (int i = 0; i < 2; ++i)
#pragma unroll
        for (int n = 0; n < 4; ++n)
#pragma unroll
            for (int q = 0; q < 4; ++q) acc[i][n][q] = 0.0f;

    uint4 A0[2], B0[2], A1[2], B1[2];
#define PLOADK(kt, Ab, Bb)                                          \
    do {                                                            \
        if ((kt) < NKTP) {                                          \
            int _o = (kt) * 32;                                     \
            Ab[0] = ldg_nc(aQ + _o);                                \
            Ab[1] = ldg_nc(aQ + 1024 + _o);                         \
            Bb[0] = ldg_nc(bQ + _o);                                \
            Bb[1] = ldg_nc(bQ + 1024 + _o);                         \
        }                                                           \
    } while (0)
#define PCOMPUTE(Ab, Bb)                                                    \
    do {                                                                    \
        _Pragma("unroll")                                                   \
        for (int i = 0; i < 2; ++i) {                                       \
            _Pragma("unroll")                                               \
            for (int g = 0; g < 2; ++g) {                                   \
                mma_fp16(acc[i][g * 2][0], acc[i][g * 2][1],                \
                         acc[i][g * 2][2], acc[i][g * 2][3],                \
                         Ab[i].x, Ab[i].y, Ab[i].z, Ab[i].w,                \
                         Bb[g].x, Bb[g].y);                                 \
                mma_fp16(acc[i][g * 2 + 1][0], acc[i][g * 2 + 1][1],        \
                         acc[i][g * 2 + 1][2], acc[i][g * 2 + 1][3],        \
                         Ab[i].x, Ab[i].y, Ab[i].z, Ab[i].w,                \
                         Bb[g].z, Bb[g].w);                                 \
            }                                                               \
        }                                                                   \
    } while (0)

    PLOADK(0, A0, B0);
#pragma unroll 1
    for (int kt = 0; kt < NKTP; kt += 2) {
        PLOADK(kt + 1, A1, B1);
        PCOMPUTE(A0, B0);
        PLOADK(kt + 2, A0, B0);
        PCOMPUTE(A1, B1);
    }
#undef PLOADK
#undef PCOMPUTE

    int gr = lane >> 2, gc2 = (lane & 3) * 2;
    const float* bias_w = bias_s + wn * 32;
#pragma unroll
    for (int i = 0; i < 2; ++i) {
#pragma unroll
        for (int half = 0; half < 2; ++half) {
            int row = m0 + wm * 32 + i * 16 + gr + half * 8;
            float* orow = C + (size_t)row * Jdim + n0 + wn * 32;
#pragma unroll
            for (int n8 = 0; n8 < 4; ++n8) {
                int col = n8 * 8 + gc2;
                float2 v;
                v.x = acc[i][n8][half * 2 + 0] + bias_w[col];
                v.y = acc[i][n8][half * 2 + 1] + bias_w[col + 1];
                *(float2*)(orow + col) = v;
            }
        }
    }
}

// ======== kernel 2: tanh(enc+pred) -> fragment tiles g_Aft ========
__global__ __launch_bounds__(128) void tanh_frag_kernel() {
    int mt = blockIdx.x;               // 0..4095
    int lane = threadIdx.x & 31;
    int w = threadIdx.x >> 5;          // 0..3
    int gr = lane >> 2, kc = (lane & 3) * 2;
    int r0 = mt * 16 + gr;             // rows r0, r0+8 share (b,t); u differs by 8
    const float* e = g_enc_out + ((size_t)(r0 >> 6) << 10);
    const float* p0 = g_pred_out + ((size_t)(((r0 >> 14) << 6) + (r0 & 63)) << 10);
    const float* p1 = p0 + ((size_t)8 << 10);   // u+8
    uint4* dst = g_Aft + (size_t)mt * (NKT * 32) + lane;
#pragma unroll 4
    for (int kt = w; kt < NKT; kt += 4) {
        int k0 = kt * 16 + kc;
        float2 eA = *(const float2*)(e + k0);
        float2 eB = *(const float2*)(e + k0 + 8);
        float2 pA0 = *(const float2*)(p0 + k0);
        float2 pB0 = *(const float2*)(p0 + k0 + 8);
        float2 pA1 = *(const float2*)(p1 + k0);
        float2 pB1 = *(const float2*)(p1 + k0 + 8);
        uint4 o;
        o.x = pack_h2(tanh_fast(eA.x + pA0.x), tanh_fast(eA.y + pA0.y));
        o.y = pack_h2(tanh_fast(eA.x + pA1.x), tanh_fast(eA.y + pA1.y));
        o.z = pack_h2(tanh_fast(eB.x + pB0.x), tanh_fast(eB.y + pB0.y));
        o.w = pack_h2(tanh_fast(eB.x + pB1.x), tanh_fast(eB.y + pB1.y));
        dst[kt * 32] = o;
    }
}

// ================= kernel 3: persistent smem-free fp16 GEMM =================
// CTA 128x128, 256 thr, 8 warps (4M x 2N), warp 32x64, 2 CTAs/SM.
// Persistent: grid = 304 (2x152 SMs); each CTA loops over tiles t += 304
// (bx-fast order preserved -> concurrent CTAs share A slabs in L2).
__global__ __launch_bounds__(256, 2) void gemm_kernel(
    const float* __restrict__ b_out, float* __restrict__ out) {
    __shared__ float bias_s[128];

    int tid = threadIdx.x;
    int lane = tid & 31;
    int wid = tid >> 5;       // 0..7
    int wm = wid >> 1;        // 0..3  (32-row slab)
    int wn = wid & 1;         // 0..1  (64-col slab)
    int gr = lane >> 2, gc2 = (lane & 3) * 2;

#pragma unroll 1
    for (int t = blockIdx.x; t < NMT * 8 / 8 * 8 / 8 * 8; t += GEMM_GRID) {
        // total tiles = 512 m-tiles-of-128 * 8 n-tiles-of-128 = 4096
        if (t >= 4096) break;
        int n0 = (t & 7) << 7;
        int m0 = (t >> 3) << 7;

        __syncthreads();          // previous tile's bias_s readers done
        if (tid < 128) bias_s[tid] = b_out[n0 + tid];
        __syncthreads();

        int mt_base = (m0 >> 4) + wm * 2;
        int nt_base = (n0 >> 4) + wn * 4;
        const uint4* aQ = g_Aft + ((size_t)mt_base << 11) + lane;
        const uint4* bQ = g_Bft + ((size_t)nt_base << 11) + lane;

        float acc[2][8][4];
#pragma unroll
        for (int mt = 0; mt < 2; ++mt)
#pragma unroll
            for (int nt = 0; nt < 8; ++nt)
#pragma unroll
                for (int q = 0; q < 4; ++q) acc[mt][nt][q] = 0.0f;

        uint4 A0[2], B0[4], A1[2], B1[4];

#define LOADK(kt, Ab, Bb)                                          \
    do {                                                           \
        if ((kt) < NKT) {                                          \
            int _o = (kt) * 32;                                    \
            _Pragma("unroll")                                      \
            for (int i = 0; i < 2; ++i) Ab[i] = ldg_nc(aQ + i * 2048 + _o); \
            _Pragma("unroll")                                      \
            for (int g = 0; g < 4; ++g) Bb[g] = ldg_nc(bQ + g * 2048 + _o); \
        }                                                          \
    } while (0)

#define COMPUTEK(Ab, Bb)                                                    \
    do {                                                                    \
        _Pragma("unroll")                                                   \
        for (int i = 0; i < 2; ++i) {                                       \
            _Pragma("unroll")                                               \
            for (int g = 0; g < 4; ++g) {                                   \
                mma_fp16(acc[i][g * 2][0], acc[i][g * 2][1],                \
                         acc[i][g * 2][2], acc[i][g * 2][3],                \
                         Ab[i].x, Ab[i].y, Ab[i].z, Ab[i].w,                \
                         Bb[g].x, Bb[g].y);                                 \
                mma_fp16(acc[i][g * 2 + 1][0], acc[i][g * 2 + 1][1],        \
                         acc[i][g * 2 + 1][2], acc[i][g * 2 + 1][3],        \
                         Ab[i].x, Ab[i].y, Ab[i].z, Ab[i].w,                \
                         Bb[g].z, Bb[g].w);                                 \
            }                                                               \
        }                                                                   \
    } while (0)

        LOADK(0, A0, B0);
#pragma unroll 1
        for (int kt = 0; kt < NKT; kt += 2) {
            LOADK(kt + 1, A1, B1);
            COMPUTEK(A0, B0);
            LOADK(kt + 2, A0, B0);
            COMPUTEK(A1, B1);
        }
#undef LOADK
#undef COMPUTEK

        // epilogue: bias + store
        const float* bias_w = bias_s + wn * 64;
#pragma unroll
        for (int mt = 0; mt < 2; ++mt) {
#pragma unroll
            for (int half = 0; half < 2; ++half) {
                int row = m0 + wm * 32 + mt * 16 + gr + half * 8;
                float* orow = out + (size_t)row * Vdim + n0 + wn * 64;
#pragma unroll
                for (int nt = 0; nt < 8; ++nt) {
                    int col = nt * 8 + gc2;
                    float2 v;
                    v.x = acc[mt][nt][half * 2 + 0] + bias_w[col];
                    v.y = acc[mt][nt][half * 2 + 1] + bias_w[col + 1];
                    *(float2*)(orow + col) = v;
                }
            }
        }
    }
}

// ================= launch =================
extern "C" void kernel_launch(void* const* d_in, const int* in_sizes, int n_in,
                              void* d_out, int out_size) {
    const float* enc    = (const float*)d_in[0];
    const float* pred   = (const float*)d_in[1];
    const float* W_enc  = (const float*)d_in[2];
    const float* b_enc  = (const float*)d_in[3];
    const float* W_pred = (const float*)d_in[4];
    const float* b_pred = (const float*)d_in[5];
    const float* W_out  = (const float*)d_in[6];
    const float* b_out  = (const float*)d_in[7];
    float* out = (float*)d_out;

    // launch 0: pack all operands to fp16 fragment tiles (10752 warp-units)
    pack_kernel<<<1344, 256>>>(enc, pred, W_enc, W_pred, W_out);
    // launch 1: proj GEMMs -> g_enc_out / g_pred_out (fp32 + bias)
    proj_gemm_kernel<<<dim3(8, 20), 256>>>(b_enc, b_pred);
    // launch 2: A = tanh(enc_out (+) pred_out) -> fragment tiles
    tanh_frag_kernel<<<NMT, 128>>>();
    // launch 3: persistent main fp16 fragment GEMM (profiled)
    gemm_kernel<<<GEMM_GRID, 256>>>(b_out, out);
}